// round 6
// baseline (speedup 1.0000x reference)
#include <cuda_runtime.h>
#include <math.h>

#define BB 16
#define NAT 256
#define KNN 24
#define FF 128
#define LL 4
#define EPSC 0.01f
#define NNODE (BB*NAT)
#define NEDGE (NNODE*KNN)
#define MT 16   // nodes per GEMM tile block

// ---------------- scratch (device globals; no allocation allowed) ----------------
__device__ float g_xbuf[2*NNODE*3];     // ping-pong positions (fractional)
__device__ int   g_idx[NEDGE];
__device__ float g_h[NNODE*FF];
__device__ float g_y[NNODE*FF];         // per-node W1 transform (pre-silu, pre-dist)
__device__ float g_vec[NEDGE*3];
__device__ float g_dist[NEDGE];
__device__ float g_u[NEDGE*3];
__device__ unsigned char g_mask[NNODE*KNN*KNN];
__device__ float g_xcart[NNODE*3];
__device__ float g_strain4[LL*BB*6];    // per-layer symmetric 3x3: 00,01,02,11,12,22
__device__ float g_tri4[LL*BB*6];
__device__ float g_rho[2*BB*9];         // ping-pong action_rho (row-major)

__constant__ int c_pc[6] = {0,0,0,1,1,2};
__constant__ int c_pd[6] = {0,1,2,1,2,2};

__device__ __forceinline__ float siluf(float a) {
    return a / (1.f + expf(-a));
}

// ---------------- init ----------------
__global__ void k_init(const float* __restrict__ x_in, float* __restrict__ out) {
    int i = blockIdx.x * blockDim.x + threadIdx.x;
    if (i < NNODE*3) { float v = x_in[i]; g_xbuf[i] = v - floorf(v); out[i] = 0.f; }
    if (i < 2*BB*9) g_rho[i] = ((i % 9) % 4 == 0) ? 1.f : 0.f;
    if (i < LL*BB*6) { g_strain4[i] = 0.f; g_tri4[i] = 0.f; }
}

// ---------------- kNN (periodic min-image, cell = I), exact top_k tie-break ----------------
__global__ void k_knn() {
    int b = blockIdx.x >> 8;
    int i = blockIdx.x & 255;
    __shared__ float sx[NAT*3];
    __shared__ float sd[NAT];
    int t = threadIdx.x;
    for (int q = t; q < NAT*3; q += 256) sx[q] = g_xbuf[b*NAT*3 + q];
    __syncthreads();
    float xi0 = sx[i*3+0], xi1 = sx[i*3+1], xi2 = sx[i*3+2];
    float d0 = sx[t*3+0] - xi0; d0 -= rintf(d0);
    float d1 = sx[t*3+1] - xi1; d1 -= rintf(d1);
    float d2 = sx[t*3+2] - xi2; d2 -= rintf(d2);
    float d = sqrtf(d0*d0 + d1*d1 + d2*d2);
    if (t == i) d += 1e6f;
    sd[t] = d;
    __syncthreads();
    int rank = 0;
    float dt = d;
    for (int j = 0; j < NAT; j++) {
        float dj = sd[j];
        rank += (dj < dt) || (dj == dt && j < t);
    }
    if (rank < KNN) g_idx[(b*NAT + i)*KNN + rank] = t;
}

// ---------------- initial edge vectors (cell = I: vec == min-image frac) ----------------
__global__ void k_edges0() {
    int e = blockIdx.x * blockDim.x + threadIdx.x;
    if (e >= NEDGE) return;
    int node = e / KNN;
    int b = node >> 8;
    int j = g_idx[e];
    const float* xb = g_xbuf + b*NAT*3;
    int n = node & 255;
    float f0 = xb[j*3+0] - xb[n*3+0]; f0 -= rintf(f0);
    float f1 = xb[j*3+1] - xb[n*3+1]; f1 -= rintf(f1);
    float f2 = xb[j*3+2] - xb[n*3+2]; f2 -= rintf(f2);
    float d  = sqrtf(f0*f0 + f1*f1 + f2*f2);
    g_vec[e*3+0] = f0; g_vec[e*3+1] = f1; g_vec[e*3+2] = f2;
    g_dist[e] = d;
    float inv = 1.f / (d + 1e-12f);
    g_u[e*3+0] = f0*inv; g_u[e*3+1] = f1*inv; g_u[e*3+2] = f2*inv;
}

// ---------------- triplet mask from INITIAL u (fixed thereafter) ----------------
__global__ void k_mask() {
    int node = blockIdx.x;
    __shared__ float su[KNN*3];
    int t = threadIdx.x;  // 64
    if (t < KNN*3) su[t] = g_u[node*KNN*3 + t];
    __syncthreads();
    for (int p = t; p < KNN*KNN; p += 64) {
        int jj = p / KNN, kk = p % KNN;
        const float* a = su + jj*3;
        const float* c = su + kk*3;
        float c0 = a[1]*c[2] - a[2]*c[1];
        float c1 = a[2]*c[0] - a[0]*c[2];
        float c2 = a[0]*c[1] - a[1]*c[0];
        g_mask[node*KNN*KNN + p] = (sqrtf(c0*c0 + c1*c1 + c2*c2) > 1e-3f) ? 1 : 0;
    }
}

// ---------------- lin1: y = h @ W1[:128,:] + b1 ; optional embedding load ----------------
__global__ void __launch_bounds__(256) k_lin1(
    const float* __restrict__ W1, const float* __restrict__ b1,
    const float* __restrict__ emb, const int* __restrict__ z)
{
    int t = threadIdx.x;
    int g = t >> 7;          // m-group 0/1
    int fo = t & 127;        // output feature
    int base = blockIdx.x * MT;
    __shared__ float sh[MT*FF];

    if (emb) {
        #pragma unroll
        for (int m = 0; m < 8; m++) {
            int node = base + g*8 + m;
            float v = emb[z[node]*FF + fo];
            sh[(g*8+m)*FF + fo] = v;
            g_h[node*FF + fo] = v;
        }
    } else {
        #pragma unroll
        for (int m = 0; m < 8; m++)
            sh[(g*8+m)*FF + fo] = g_h[(base + g*8 + m)*FF + fo];
    }
    __syncthreads();

    float acc[8];
    float bg = b1[fo];
    #pragma unroll
    for (int m = 0; m < 8; m++) acc[m] = bg;

    #pragma unroll 2
    for (int f = 0; f < FF; f += 4) {
        float w0 = W1[(f+0)*FF + fo];
        float w1 = W1[(f+1)*FF + fo];
        float w2 = W1[(f+2)*FF + fo];
        float w3 = W1[(f+3)*FF + fo];
        #pragma unroll
        for (int m = 0; m < 8; m++) {
            float4 hv = *(const float4*)(sh + (g*8+m)*FF + f);
            acc[m] += hv.x*w0 + hv.y*w1 + hv.z*w2 + hv.w*w3;
        }
    }
    #pragma unroll
    for (int m = 0; m < 8; m++) g_y[(base + g*8 + m)*FF + fo] = acc[m];
}

// ---------------- fused: aggr (msum) + lin2 (h update) + lin1 of next layer ----------------
__global__ void __launch_bounds__(256) k_fusedA(
    const float* __restrict__ wl_row,   // current layer W1 row 128 (dist weights)
    const float* __restrict__ W2, const float* __restrict__ b2,
    const float* __restrict__ W1n, const float* __restrict__ b1n)
{
    int t = threadIdx.x;
    int g = t >> 7;
    int fo = t & 127;
    int base = blockIdx.x * MT;
    int b = base >> 8;   // uniform: 16 tiles per batch

    __shared__ float shm[MT*FF];
    __shared__ float shh[MT*FF];
    __shared__ float sdist[MT*KNN];
    __shared__ int   sjj[MT*KNN];

    for (int q = t; q < MT*KNN; q += 256) {
        sdist[q] = g_dist[base*KNN + q];
        sjj[q]   = g_idx[base*KNN + q];
    }
    __syncthreads();

    // aggr: msum[m][fo] = sum_k silu(y[j_k] + dist_k * wl)
    float wl = wl_row[fo];
    const float* yb = g_y + b*NAT*FF;
    #pragma unroll
    for (int m = 0; m < 8; m++) {
        int mm = g*8 + m;
        float s = 0.f;
        #pragma unroll 4
        for (int k = 0; k < KNN; k++) {
            int j = sjj[mm*KNN + k];
            float d = sdist[mm*KNN + k];
            s += siluf(yb[j*FF + fo] + d*wl);
        }
        shm[mm*FF + fo] = s;
    }
    __syncthreads();

    // lin2: h += silu(msum @ W2 + b2)
    float acc[8];
    float bg = b2[fo];
    #pragma unroll
    for (int m = 0; m < 8; m++) acc[m] = bg;
    #pragma unroll 2
    for (int f = 0; f < FF; f += 4) {
        float w0 = W2[(f+0)*FF + fo];
        float w1 = W2[(f+1)*FF + fo];
        float w2 = W2[(f+2)*FF + fo];
        float w3 = W2[(f+3)*FF + fo];
        #pragma unroll
        for (int m = 0; m < 8; m++) {
            float4 mv = *(const float4*)(shm + (g*8+m)*FF + f);
            acc[m] += mv.x*w0 + mv.y*w1 + mv.z*w2 + mv.w*w3;
        }
    }
    #pragma unroll
    for (int m = 0; m < 8; m++) {
        int node = base + g*8 + m;
        float hn = g_h[node*FF + fo] + siluf(acc[m]);
        g_h[node*FF + fo] = hn;
        shh[(g*8+m)*FF + fo] = hn;
    }

    // lin1 of next layer (reads only this tile's h, already in shared)
    if (W1n) {
        __syncthreads();
        float bg1 = b1n[fo];
        #pragma unroll
        for (int m = 0; m < 8; m++) acc[m] = bg1;
        #pragma unroll 2
        for (int f = 0; f < FF; f += 4) {
            float w0 = W1n[(f+0)*FF + fo];
            float w1 = W1n[(f+1)*FF + fo];
            float w2 = W1n[(f+2)*FF + fo];
            float w3 = W1n[(f+3)*FF + fo];
            #pragma unroll
            for (int m = 0; m < 8; m++) {
                float4 hv = *(const float4*)(shh + (g*8+m)*FF + f);
                acc[m] += hv.x*w0 + hv.y*w1 + hv.z*w2 + hv.w*w3;
            }
        }
        #pragma unroll
        for (int m = 0; m < 8; m++) g_y[(base + g*8 + m)*FF + fo] = acc[m];
    }
}

// ---------------- edge weights + strain/tri partials (per-layer buffers) + x_cart ----------------
__global__ void __launch_bounds__(128) k_edgew(
    const float* __restrict__ awe, const float* __restrict__ awp, int l)
{
    const float* h = g_h;
    int node = blockIdx.x;
    int b = node >> 8;
    int t = threadIdx.x;
    int lane = t & 31, w = t >> 5;

    __shared__ float sh_hi[FF], sh_awe[FF], sh_awp[FF];
    __shared__ float sh_we[KNN], sh_wp[KNN];
    __shared__ float su[KNN*3], sv[KNN*3];
    __shared__ float sT[6];

    sh_hi[t]  = h[node*FF + t];
    sh_awe[t] = awe[t];
    sh_awp[t] = awp[t];
    if (t < KNN*3) { su[t] = g_u[node*KNN*3 + t]; sv[t] = g_vec[node*KNN*3 + t]; }
    if (t < 6) sT[t] = 0.f;
    __syncthreads();

    #pragma unroll
    for (int q = 0; q < 6; q++) {
        int k = w*6 + q;
        int j = g_idx[node*KNN + k];
        const float* hj = h + (b*NAT + j)*FF;
        float de = 0.f, dp = 0.f;
        #pragma unroll
        for (int m = 0; m < 4; m++) {
            int f = lane + 32*m;
            float e = sh_hi[f] + hj[f];
            de += e * sh_awe[f];
            dp += e * sh_awp[f];
        }
        #pragma unroll
        for (int o = 16; o; o >>= 1) {
            de += __shfl_xor_sync(0xffffffffu, de, o);
            dp += __shfl_xor_sync(0xffffffffu, dp, o);
        }
        if (lane == 0) { sh_we[k] = tanhf(de); sh_wp[k] = tanhf(dp); }
    }
    __syncthreads();

    if (t < 6) {
        int c = c_pc[t], d = c_pd[t];
        float s = 0.f;
        #pragma unroll
        for (int k = 0; k < KNN; k++) s += sh_we[k] * su[k*3+c] * su[k*3+d];
        atomicAdd(&g_strain4[l*BB*6 + b*6 + t], s);
    } else if (t >= 16 && t < 19) {
        int c = t - 16;
        float s = 0.f;
        #pragma unroll
        for (int k = 0; k < KNN; k++) s += sh_wp[k] * sv[k*3+c];
        g_xcart[node*3 + c] = EPSC * s;
    }

    float T0=0.f,T1=0.f,T2=0.f,T3=0.f,T4=0.f,T5=0.f;
    const unsigned char* mp = g_mask + node*KNN*KNN;
    for (int p = t; p < KNN*KNN; p += 128) {
        if (!mp[p]) continue;
        int jj = p / KNN, kk = p - jj*KNN;
        float wjk = sh_we[jj] * sh_we[kk];
        const float* a = su + jj*3;
        const float* c = su + kk*3;
        float c0 = a[1]*c[2] - a[2]*c[1];
        float c1 = a[2]*c[0] - a[0]*c[2];
        float c2 = a[0]*c[1] - a[1]*c[0];
        T0 += wjk*c0*c0; T1 += wjk*c0*c1; T2 += wjk*c0*c2;
        T3 += wjk*c1*c1; T4 += wjk*c1*c2; T5 += wjk*c2*c2;
    }
    #pragma unroll
    for (int o = 16; o; o >>= 1) {
        T0 += __shfl_xor_sync(0xffffffffu, T0, o);
        T1 += __shfl_xor_sync(0xffffffffu, T1, o);
        T2 += __shfl_xor_sync(0xffffffffu, T2, o);
        T3 += __shfl_xor_sync(0xffffffffu, T3, o);
        T4 += __shfl_xor_sync(0xffffffffu, T4, o);
        T5 += __shfl_xor_sync(0xffffffffu, T5, o);
    }
    if (lane == 0) {
        atomicAdd(&sT[0], T0); atomicAdd(&sT[1], T1); atomicAdd(&sT[2], T2);
        atomicAdd(&sT[3], T3); atomicAdd(&sT[4], T4); atomicAdd(&sT[5], T5);
    }
    __syncthreads();
    if (t < 6) atomicAdd(&g_tri4[l*BB*6 + b*6 + t], sT[t]);
}

// ---------------- fused action + position update + edge recompute ----------------
// Each block (256 edges, single batch) recomputes the 3x3 action/inverse redundantly.
__global__ void __launch_bounds__(256) k_pos_edges(int l, int do_edges, float* __restrict__ out)
{
    int e = blockIdx.x * 256 + threadIdx.x;   // NEDGE = 384*256
    int node = e / KNN;
    int k = e - node*KNN;
    int b = node >> 8;                         // uniform per block (6144 edges/batch, 24 blocks)
    int p = l & 1;

    __shared__ float s_iv[9];    // inv(rho_old) = inv(old geo_cell)
    __shared__ float s_cell[9];  // new geo_cell = rho_new

    if (threadIdx.x == 0) {
        float s6[6], t6[6];
        #pragma unroll
        for (int i = 0; i < 6; i++) {
            s6[i] = g_strain4[l*BB*6 + b*6 + i];
            t6[i] = g_tri4[l*BB*6 + b*6 + i];
        }
        const float NK  = (float)(NAT*KNN);
        const float NKK = (float)(NAT*KNN*KNN);
        float P[9];
        P[0] = s6[0]/NK + t6[0]/NKK;
        P[1] = s6[1]/NK + t6[1]/NKK; P[3] = P[1];
        P[2] = s6[2]/NK + t6[2]/NKK; P[6] = P[2];
        P[4] = s6[3]/NK + t6[3]/NKK;
        P[5] = s6[4]/NK + t6[4]/NKK; P[7] = P[5];
        P[8] = s6[5]/NK + t6[5]/NKK;
        float A[9];
        #pragma unroll
        for (int i = 0; i < 9; i++) A[i] = EPSC*P[i] + ((i % 4 == 0) ? 1.f : 0.f);
        float R[9], Rn[9];
        #pragma unroll
        for (int i = 0; i < 9; i++) R[i] = g_rho[p*BB*9 + b*9 + i];
        #pragma unroll
        for (int i = 0; i < 3; i++)
            #pragma unroll
            for (int kk = 0; kk < 3; kk++)
                Rn[i*3+kk] = A[i*3+0]*R[0+kk] + A[i*3+1]*R[3+kk] + A[i*3+2]*R[6+kk];
        // inverse of OLD geo_cell (= rho_old; I at l=0)
        float det = R[0]*(R[4]*R[8]-R[5]*R[7]) - R[1]*(R[3]*R[8]-R[5]*R[6]) + R[2]*(R[3]*R[7]-R[4]*R[6]);
        float id = 1.f/det;
        s_iv[0]=(R[4]*R[8]-R[5]*R[7])*id;
        s_iv[1]=(R[2]*R[7]-R[1]*R[8])*id;
        s_iv[2]=(R[1]*R[5]-R[2]*R[4])*id;
        s_iv[3]=(R[5]*R[6]-R[3]*R[8])*id;
        s_iv[4]=(R[0]*R[8]-R[2]*R[6])*id;
        s_iv[5]=(R[2]*R[3]-R[0]*R[5])*id;
        s_iv[6]=(R[3]*R[7]-R[4]*R[6])*id;
        s_iv[7]=(R[1]*R[6]-R[0]*R[7])*id;
        s_iv[8]=(R[0]*R[4]-R[1]*R[3])*id;
        #pragma unroll
        for (int i = 0; i < 9; i++) s_cell[i] = Rn[i];
        if (blockIdx.x % 24 == 0) {   // designated writer for this batch
            #pragma unroll
            for (int i = 0; i < 9; i++) g_rho[(p^1)*BB*9 + b*9 + i] = Rn[i];
            if (!do_edges) {          // last layer: emit rho_prime
                #pragma unroll
                for (int i = 0; i < 9; i++) out[NNODE*3 + b*9 + i] = Rn[i];
            }
        }
    }
    __syncthreads();

    const float* xo = g_xbuf + p*NNODE*3;
    float*       xn = g_xbuf + (p^1)*NNODE*3;
    int j  = g_idx[e];
    int jn = b*NAT + j;

    float cn0 = g_xcart[node*3+0], cn1 = g_xcart[node*3+1], cn2 = g_xcart[node*3+2];
    float xnn[3];
    #pragma unroll
    for (int d = 0; d < 3; d++)
        xnn[d] = xo[node*3+d] + cn0*s_iv[0*3+d] + cn1*s_iv[1*3+d] + cn2*s_iv[2*3+d];

    if (k == 0) {
        #pragma unroll
        for (int d = 0; d < 3; d++) {
            if (do_edges) xn[node*3+d] = xnn[d];
            out[node*3+d] += g_xcart[node*3+d];   // traj_sum += x_cart
        }
    }

    if (do_edges) {
        float cj0 = g_xcart[jn*3+0], cj1 = g_xcart[jn*3+1], cj2 = g_xcart[jn*3+2];
        float f[3];
        #pragma unroll
        for (int d = 0; d < 3; d++) {
            float xj = xo[jn*3+d] + cj0*s_iv[0*3+d] + cj1*s_iv[1*3+d] + cj2*s_iv[2*3+d];
            float fd = xj - xnn[d];
            f[d] = fd - rintf(fd);
        }
        float v0 = f[0]*s_cell[0] + f[1]*s_cell[3] + f[2]*s_cell[6];
        float v1 = f[0]*s_cell[1] + f[1]*s_cell[4] + f[2]*s_cell[7];
        float v2 = f[0]*s_cell[2] + f[1]*s_cell[5] + f[2]*s_cell[8];
        float d  = sqrtf(v0*v0 + v1*v1 + v2*v2);
        g_vec[e*3+0] = v0; g_vec[e*3+1] = v1; g_vec[e*3+2] = v2;
        g_dist[e] = d;
        float inv = 1.f / (d + 1e-12f);
        g_u[e*3+0] = v0*inv; g_u[e*3+1] = v1*inv; g_u[e*3+2] = v2*inv;
    }
}

// ---------------- launch ----------------
extern "C" void kernel_launch(void* const* d_in, const int* in_sizes, int n_in,
                              void* d_out, int out_size) {
    const float* x_in = (const float*)d_in[1];
    const int*   z    = (const int*)  d_in[2];
    const float* emb  = (const float*)d_in[4];
    const float* mW1  = (const float*)d_in[5];
    const float* mb1  = (const float*)d_in[6];
    const float* mW2  = (const float*)d_in[7];
    const float* mb2  = (const float*)d_in[8];
    const float* uW1  = (const float*)d_in[9];
    const float* ub1  = (const float*)d_in[10];
    const float* uW2  = (const float*)d_in[11];
    const float* ub2  = (const float*)d_in[12];
    const float* awe  = (const float*)d_in[13];
    const float* awp  = (const float*)d_in[14];
    float* out = (float*)d_out;

    const int NG  = NNODE / MT;       // 256 GEMM tiles
    const int SZ1 = (FF+1)*FF;

    k_init  <<<48, 256>>>(x_in, out);
    k_knn   <<<NNODE, 256>>>();
    k_edges0<<<NEDGE/256, 256>>>();
    k_mask  <<<NNODE, 64>>>();

    k_lin1<<<NG, 256>>>(mW1, mb1, emb, z);
    for (int l = 0; l < LL; l++) {
        const float* W1n = (l < 3) ? (mW1 + (l+1)*SZ1) : uW1;
        const float* b1n = (l < 3) ? (mb1 + (l+1)*FF)  : ub1;
        k_fusedA<<<NG, 256>>>(mW1 + l*SZ1 + FF*FF, mW2 + l*FF*FF, mb2 + l*FF, W1n, b1n);
    }
    for (int l = 0; l < LL; l++) {
        const float* W1n = (l < 3) ? (uW1 + (l+1)*SZ1) : (const float*)0;
        const float* b1n = (l < 3) ? (ub1 + (l+1)*FF)  : (const float*)0;
        k_fusedA<<<NG, 256>>>(uW1 + l*SZ1 + FF*FF, uW2 + l*FF*FF, ub2 + l*FF, W1n, b1n);
        k_edgew<<<NNODE, 128>>>(awe + l*FF, awp + l*FF, l);
        k_pos_edges<<<NEDGE/256, 256>>>(l, (l < LL-1) ? 1 : 0, out);
    }
}

// round 7
// speedup vs baseline: 1.4201x; 1.4201x over previous
#include <cuda_runtime.h>
#include <math.h>

#define BB 16
#define NAT 256
#define KNN 24
#define FF 128
#define LL 4
#define EPSC 0.01f
#define NNODE (BB*NAT)
#define NEDGE (NNODE*KNN)

// ---------------- scratch (device globals; no allocation allowed) ----------------
__device__ float g_x[NNODE*3];
__device__ int   g_idx[NEDGE];
__device__ float g_h[NNODE*FF];
__device__ float g_y[2*NNODE*FF];    // ping-pong per-node W1 transform
__device__ float g_vec[NEDGE*3];
__device__ float g_dist[NEDGE];
__device__ float g_u[NEDGE*3];
__device__ unsigned char g_mask[NNODE*KNN*KNN];
__device__ float g_xcart[NNODE*3];
__device__ float g_strain[BB*6];   // symmetric 3x3 packed: 00,01,02,11,12,22
__device__ float g_tri[BB*6];
__device__ float g_cell[BB*9];     // geo_cell (row-major)
__device__ float g_rho[BB*9];      // action_rho
__device__ float g_invcell[BB*9];

__constant__ int c_pc[6] = {0,0,0,1,1,2};
__constant__ int c_pd[6] = {0,1,2,1,2,2};

__device__ __forceinline__ float siluf(float a) {
    return a / (1.f + expf(-a));
}

// ---------------- init: x = mod(x,1), cells = I, accumulators = 0, traj = 0 ----------------
__global__ void k_init(const float* __restrict__ x_in, float* __restrict__ out) {
    int i = blockIdx.x * blockDim.x + threadIdx.x;
    if (i < NNODE*3) { float v = x_in[i]; g_x[i] = v - floorf(v); out[i] = 0.f; }
    if (i < BB*9) {
        float id = ((i % 9) % 4 == 0) ? 1.f : 0.f;
        g_cell[i] = id; g_rho[i] = id;
    }
    if (i < BB*6) { g_strain[i] = 0.f; g_tri[i] = 0.f; }
}

// ---------------- kNN (periodic min-image, cell = I), exact top_k tie-break ----------------
__global__ void k_knn() {
    int b = blockIdx.x >> 8;
    int i = blockIdx.x & 255;
    __shared__ float sx[NAT*3];
    __shared__ float sd[NAT];
    int t = threadIdx.x;
    for (int q = t; q < NAT*3; q += 256) sx[q] = g_x[b*NAT*3 + q];
    __syncthreads();
    float xi0 = sx[i*3+0], xi1 = sx[i*3+1], xi2 = sx[i*3+2];
    float d0 = sx[t*3+0] - xi0; d0 -= rintf(d0);
    float d1 = sx[t*3+1] - xi1; d1 -= rintf(d1);
    float d2 = sx[t*3+2] - xi2; d2 -= rintf(d2);
    float d = sqrtf(d0*d0 + d1*d1 + d2*d2);
    if (t == i) d += 1e6f;
    sd[t] = d;
    __syncthreads();
    int rank = 0;
    float dt = d;
    for (int j = 0; j < NAT; j++) {
        float dj = sd[j];
        rank += (dj < dt) || (dj == dt && j < t);
    }
    if (rank < KNN) g_idx[(b*NAT + i)*KNN + rank] = t;
}

// ---------------- edge vectors: vec = (frac - round(frac)) @ cell ----------------
__global__ void k_edges() {
    int e = blockIdx.x * blockDim.x + threadIdx.x;
    if (e >= NEDGE) return;
    int b = e / (NAT*KNN);
    int n = (e / KNN) & 255;
    int j = g_idx[e];
    const float* xb = g_x + b*NAT*3;
    float f0 = xb[j*3+0] - xb[n*3+0]; f0 -= rintf(f0);
    float f1 = xb[j*3+1] - xb[n*3+1]; f1 -= rintf(f1);
    float f2 = xb[j*3+2] - xb[n*3+2]; f2 -= rintf(f2);
    const float* C = g_cell + b*9;
    float v0 = f0*C[0] + f1*C[3] + f2*C[6];
    float v1 = f0*C[1] + f1*C[4] + f2*C[7];
    float v2 = f0*C[2] + f1*C[5] + f2*C[8];
    float d  = sqrtf(v0*v0 + v1*v1 + v2*v2);
    g_vec[e*3+0] = v0; g_vec[e*3+1] = v1; g_vec[e*3+2] = v2;
    g_dist[e] = d;
    float inv = 1.f / (d + 1e-12f);
    g_u[e*3+0] = v0*inv; g_u[e*3+1] = v1*inv; g_u[e*3+2] = v2*inv;
}

// ---------------- triplet mask from INITIAL u (fixed thereafter) ----------------
__global__ void k_mask() {
    int node = blockIdx.x;
    __shared__ float su[KNN*3];
    int t = threadIdx.x;  // 64
    if (t < KNN*3) su[t] = g_u[node*KNN*3 + t];
    __syncthreads();
    for (int p = t; p < KNN*KNN; p += 64) {
        int jj = p / KNN, kk = p % KNN;
        const float* a = su + jj*3;
        const float* c = su + kk*3;
        float c0 = a[1]*c[2] - a[2]*c[1];
        float c1 = a[2]*c[0] - a[0]*c[2];
        float c2 = a[0]*c[1] - a[1]*c[0];
        g_mask[node*KNN*KNN + p] = (sqrtf(c0*c0 + c1*c1 + c2*c2) > 1e-3f) ? 1 : 0;
    }
}

// ---------------- first lin1 (per node): h = emb[z]; y = h @ W1[:128,:] + b1 ----------------
__global__ void __launch_bounds__(128) k_lin1n(
    const float* __restrict__ W1, const float* __restrict__ b1,
    const float* __restrict__ emb, const int* __restrict__ z)
{
    int node = blockIdx.x;
    int t = threadIdx.x;
    __shared__ float shh[FF];
    float hv = emb[z[node]*FF + t];
    g_h[node*FF + t] = hv;
    shh[t] = hv;
    __syncthreads();

    float acc = b1[t];
    #pragma unroll 4
    for (int f = 0; f < FF; f += 4) {
        float w0 = W1[(f+0)*FF + t];
        float w1 = W1[(f+1)*FF + t];
        float w2 = W1[(f+2)*FF + t];
        float w3 = W1[(f+3)*FF + t];
        float4 hv4 = *(const float4*)(shh + f);
        acc += hv4.x*w0 + hv4.y*w1 + hv4.z*w2 + hv4.w*w3;
    }
    g_y[node*FF + t] = acc;
}

// ---------------- fused MPNN layer (per node): aggr -> lin2 -> h += -> lin1(next) ----------
// Reads y from parity p, writes next-layer y to parity p^1 (cross-block race avoided).
__global__ void __launch_bounds__(128) k_fusedL(
    const float* __restrict__ wl_row,   // W1 row 128 (dist weights) of current layer
    const float* __restrict__ W2, const float* __restrict__ b2,
    const float* __restrict__ W1n, const float* __restrict__ b1n, int p)
{
    int node = blockIdx.x;
    int b = node >> 8;
    int t = threadIdx.x;

    __shared__ float sdist[KNN];
    __shared__ int   sj[KNN];
    __shared__ float shm[FF];
    __shared__ float shh[FF];

    if (t < KNN) { sdist[t] = g_dist[node*KNN + t]; sj[t] = g_idx[node*KNN + t]; }
    __syncthreads();

    // aggr: msum = sum_k silu(y[j_k] + dist_k * wl)
    const float* yb = g_y + p*NNODE*FF + b*NAT*FF;
    float wl = wl_row[t];
    float s = 0.f;
    #pragma unroll 4
    for (int k = 0; k < KNN; k++) {
        float yv = yb[sj[k]*FF + t];
        s += siluf(yv + sdist[k]*wl);
    }
    shm[t] = s;
    __syncthreads();

    // lin2: h += silu(msum @ W2 + b2)
    float acc = b2[t];
    #pragma unroll 4
    for (int f = 0; f < FF; f += 4) {
        float w0 = W2[(f+0)*FF + t];
        float w1 = W2[(f+1)*FF + t];
        float w2 = W2[(f+2)*FF + t];
        float w3 = W2[(f+3)*FF + t];
        float4 mv = *(const float4*)(shm + f);
        acc += mv.x*w0 + mv.y*w1 + mv.z*w2 + mv.w*w3;
    }
    float hn = g_h[node*FF + t] + siluf(acc);
    g_h[node*FF + t] = hn;

    // lin1 of next layer (node-local h)
    if (W1n) {
        shh[t] = hn;
        __syncthreads();
        float a1 = b1n[t];
        #pragma unroll 4
        for (int f = 0; f < FF; f += 4) {
            float w0 = W1n[(f+0)*FF + t];
            float w1 = W1n[(f+1)*FF + t];
            float w2 = W1n[(f+2)*FF + t];
            float w3 = W1n[(f+3)*FF + t];
            float4 hv4 = *(const float4*)(shh + f);
            a1 += hv4.x*w0 + hv4.y*w1 + hv4.z*w2 + hv4.w*w3;
        }
        g_y[(p^1)*NNODE*FF + node*FF + t] = a1;
    }
}

// ---------------- edge weights + strain/tri partials + x_cart ----------------
__global__ void __launch_bounds__(128) k_edgew(
    const float* __restrict__ awe, const float* __restrict__ awp)
{
    const float* h = g_h;
    int node = blockIdx.x;
    int b = node >> 8;
    int t = threadIdx.x;
    int lane = t & 31, w = t >> 5;

    __shared__ float sh_hi[FF], sh_awe[FF], sh_awp[FF];
    __shared__ float sh_we[KNN], sh_wp[KNN];
    __shared__ float su[KNN*3], sv[KNN*3];
    __shared__ float sT[6];

    sh_hi[t]  = h[node*FF + t];
    sh_awe[t] = awe[t];
    sh_awp[t] = awp[t];
    if (t < KNN*3) { su[t] = g_u[node*KNN*3 + t]; sv[t] = g_vec[node*KNN*3 + t]; }
    if (t < 6) sT[t] = 0.f;
    __syncthreads();

    // w_e, w_p : each warp handles 6 edges, 32-lane dot over F
    #pragma unroll
    for (int q = 0; q < 6; q++) {
        int k = w*6 + q;
        int j = g_idx[node*KNN + k];
        const float* hj = h + (b*NAT + j)*FF;
        float de = 0.f, dp = 0.f;
        #pragma unroll
        for (int m = 0; m < 4; m++) {
            int f = lane + 32*m;
            float e = sh_hi[f] + hj[f];
            de += e * sh_awe[f];
            dp += e * sh_awp[f];
        }
        #pragma unroll
        for (int o = 16; o; o >>= 1) {
            de += __shfl_xor_sync(0xffffffffu, de, o);
            dp += __shfl_xor_sync(0xffffffffu, dp, o);
        }
        if (lane == 0) { sh_we[k] = tanhf(de); sh_wp[k] = tanhf(dp); }
    }
    __syncthreads();

    // strain partial (symmetric 6) and x_cart
    if (t < 6) {
        int c = c_pc[t], d = c_pd[t];
        float s = 0.f;
        #pragma unroll
        for (int k = 0; k < KNN; k++) s += sh_we[k] * su[k*3+c] * su[k*3+d];
        atomicAdd(&g_strain[b*6 + t], s);
    } else if (t >= 16 && t < 19) {
        int c = t - 16;
        float s = 0.f;
        #pragma unroll
        for (int k = 0; k < KNN; k++) s += sh_wp[k] * sv[k*3+c];
        g_xcart[node*3 + c] = EPSC * s;
    }

    // tri partial over 576 pairs (cross products on the fly, symmetric 6)
    float T0=0.f,T1=0.f,T2=0.f,T3=0.f,T4=0.f,T5=0.f;
    const unsigned char* mp = g_mask + node*KNN*KNN;
    for (int p = t; p < KNN*KNN; p += 128) {
        if (!mp[p]) continue;
        int jj = p / KNN, kk = p - jj*KNN;
        float wjk = sh_we[jj] * sh_we[kk];
        const float* a = su + jj*3;
        const float* c = su + kk*3;
        float c0 = a[1]*c[2] - a[2]*c[1];
        float c1 = a[2]*c[0] - a[0]*c[2];
        float c2 = a[0]*c[1] - a[1]*c[0];
        T0 += wjk*c0*c0; T1 += wjk*c0*c1; T2 += wjk*c0*c2;
        T3 += wjk*c1*c1; T4 += wjk*c1*c2; T5 += wjk*c2*c2;
    }
    #pragma unroll
    for (int o = 16; o; o >>= 1) {
        T0 += __shfl_xor_sync(0xffffffffu, T0, o);
        T1 += __shfl_xor_sync(0xffffffffu, T1, o);
        T2 += __shfl_xor_sync(0xffffffffu, T2, o);
        T3 += __shfl_xor_sync(0xffffffffu, T3, o);
        T4 += __shfl_xor_sync(0xffffffffu, T4, o);
        T5 += __shfl_xor_sync(0xffffffffu, T5, o);
    }
    if (lane == 0) {
        atomicAdd(&sT[0], T0); atomicAdd(&sT[1], T1); atomicAdd(&sT[2], T2);
        atomicAdd(&sT[3], T3); atomicAdd(&sT[4], T4); atomicAdd(&sT[5], T5);
    }
    __syncthreads();
    if (t < 6) atomicAdd(&g_tri[b*6 + t], sT[t]);
}

// ---------------- per-batch action update; inv(old cell); zero accumulators ----------------
__global__ void k_action(int is_last, float* __restrict__ out) {
    int b = blockIdx.x;
    if (threadIdx.x != 0) return;
    float s6[6], t6[6];
    #pragma unroll
    for (int i = 0; i < 6; i++) {
        s6[i] = g_strain[b*6+i]; t6[i] = g_tri[b*6+i];
        g_strain[b*6+i] = 0.f;   g_tri[b*6+i] = 0.f;
    }
    const float NK  = (float)(NAT*KNN);
    const float NKK = (float)(NAT*KNN*KNN);
    float P[9];
    P[0] = s6[0]/NK + t6[0]/NKK;
    P[1] = s6[1]/NK + t6[1]/NKK; P[3] = P[1];
    P[2] = s6[2]/NK + t6[2]/NKK; P[6] = P[2];
    P[4] = s6[3]/NK + t6[3]/NKK;
    P[5] = s6[4]/NK + t6[4]/NKK; P[7] = P[5];
    P[8] = s6[5]/NK + t6[5]/NKK;
    float A[9];
    #pragma unroll
    for (int i = 0; i < 9; i++) A[i] = EPSC*P[i] + ((i % 4 == 0) ? 1.f : 0.f);
    float R[9], C[9], Rn[9];
    #pragma unroll
    for (int i = 0; i < 9; i++) { R[i] = g_rho[b*9+i]; C[i] = g_cell[b*9+i]; }
    #pragma unroll
    for (int i = 0; i < 3; i++)
        #pragma unroll
        for (int k = 0; k < 3; k++)
            Rn[i*3+k] = A[i*3+0]*R[0+k] + A[i*3+1]*R[3+k] + A[i*3+2]*R[6+k];
    // inverse of OLD geo_cell (adjugate)
    float det = C[0]*(C[4]*C[8]-C[5]*C[7]) - C[1]*(C[3]*C[8]-C[5]*C[6]) + C[2]*(C[3]*C[7]-C[4]*C[6]);
    float id = 1.f/det;
    float IV[9];
    IV[0]=(C[4]*C[8]-C[5]*C[7])*id;
    IV[1]=(C[2]*C[7]-C[1]*C[8])*id;
    IV[2]=(C[1]*C[5]-C[2]*C[4])*id;
    IV[3]=(C[5]*C[6]-C[3]*C[8])*id;
    IV[4]=(C[0]*C[8]-C[2]*C[6])*id;
    IV[5]=(C[2]*C[3]-C[0]*C[5])*id;
    IV[6]=(C[3]*C[7]-C[4]*C[6])*id;
    IV[7]=(C[1]*C[6]-C[0]*C[7])*id;
    IV[8]=(C[0]*C[4]-C[1]*C[3])*id;
    #pragma unroll
    for (int i = 0; i < 9; i++) {
        g_invcell[b*9+i] = IV[i];
        g_rho[b*9+i] = Rn[i];
        g_cell[b*9+i] = Rn[i];   // geo_cell = rho_prime (cell0 = I)
    }
    if (is_last) {
        #pragma unroll
        for (int i = 0; i < 9; i++) out[NNODE*3 + b*9 + i] = Rn[i];
    }
}

// ---------------- position update: x += x_cart @ inv(old cell); traj += x_cart ----------------
__global__ void k_pos(float* __restrict__ out) {
    int node = blockIdx.x * blockDim.x + threadIdx.x;
    if (node >= NNODE) return;
    int b = node >> 8;
    float xc0 = g_xcart[node*3+0];
    float xc1 = g_xcart[node*3+1];
    float xc2 = g_xcart[node*3+2];
    const float* iv = g_invcell + b*9;
    float xf0 = xc0*iv[0] + xc1*iv[3] + xc2*iv[6];
    float xf1 = xc0*iv[1] + xc1*iv[4] + xc2*iv[7];
    float xf2 = xc0*iv[2] + xc1*iv[5] + xc2*iv[8];
    g_x[node*3+0] += xf0;
    g_x[node*3+1] += xf1;
    g_x[node*3+2] += xf2;
    out[node*3+0] += xc0;
    out[node*3+1] += xc1;
    out[node*3+2] += xc2;
}

// ---------------- launch ----------------
extern "C" void kernel_launch(void* const* d_in, const int* in_sizes, int n_in,
                              void* d_out, int out_size) {
    const float* x_in = (const float*)d_in[1];
    const int*   z    = (const int*)  d_in[2];
    const float* emb  = (const float*)d_in[4];
    const float* mW1  = (const float*)d_in[5];
    const float* mb1  = (const float*)d_in[6];
    const float* mW2  = (const float*)d_in[7];
    const float* mb2  = (const float*)d_in[8];
    const float* uW1  = (const float*)d_in[9];
    const float* ub1  = (const float*)d_in[10];
    const float* uW2  = (const float*)d_in[11];
    const float* ub2  = (const float*)d_in[12];
    const float* awe  = (const float*)d_in[13];
    const float* awp  = (const float*)d_in[14];
    float* out = (float*)d_out;

    const int SZ1 = (FF+1)*FF;

    k_init <<<48, 256>>>(x_in, out);
    k_knn  <<<NNODE, 256>>>();
    k_edges<<<(NEDGE + 255)/256, 256>>>();
    k_mask <<<NNODE, 64>>>();

    k_lin1n<<<NNODE, 128>>>(mW1, mb1, emb, z);
    int p = 0;
    for (int l = 0; l < LL; l++) {
        const float* W1n = (l < 3) ? (mW1 + (l+1)*SZ1) : uW1;
        const float* b1n = (l < 3) ? (mb1 + (l+1)*FF)  : ub1;
        k_fusedL<<<NNODE, 128>>>(mW1 + l*SZ1 + FF*FF, mW2 + l*FF*FF, mb2 + l*FF, W1n, b1n, p);
        p ^= 1;
    }
    for (int l = 0; l < LL; l++) {
        const float* W1n = (l < 3) ? (uW1 + (l+1)*SZ1) : (const float*)0;
        const float* b1n = (l < 3) ? (ub1 + (l+1)*FF)  : (const float*)0;
        k_fusedL<<<NNODE, 128>>>(uW1 + l*SZ1 + FF*FF, uW2 + l*FF*FF, ub2 + l*FF, W1n, b1n, p);
        p ^= 1;
        k_edgew<<<NNODE, 128>>>(awe + l*FF, awp + l*FF);
        k_action<<<BB, 32>>>(l == LL-1 ? 1 : 0, out);
        k_pos  <<<(NNODE + 255)/256, 256>>>(out);
        if (l < LL-1) k_edges<<<(NEDGE + 255)/256, 256>>>();
    }
}